// round 15
// baseline (speedup 1.0000x reference)
#include <cuda_runtime.h>
#include <cuda_fp16.h>
#include <cstdint>

// ============================================================================
// Problem constants
// ============================================================================
#define BDIM   32768
#define DDIM   1024
#define XCLIP  7.0f                   // |x| clip for s8 quant (P(|x|>7)~1e-12)

// ============================================================================
// Scratch (device globals — no runtime allocation allowed)
// ============================================================================
__device__ float g_S0t[DDIM * DDIM];          // softmax(P0)^T fp32
__device__ float g_M  [DDIM * DDIM];          // final composed matrix fp32
__device__ __half g_S1[DDIM * DDIM];
__device__ __half g_S2[DDIM * DDIM];
__device__ __half g_S3[DDIM * DDIM];
__device__ __half g_T0a[DDIM * DDIM];
__device__ __half g_T0b[DDIM * DDIM];
__device__ int8_t g_M8[DDIM * DDIM];          // s8(M * 127/amax)
__device__ int8_t g_x8[(size_t)BDIM * DDIM];  // s8(x * 127/XCLIP)
__device__ unsigned g_amax_bits;              // bits of amax(|M|)

// ============================================================================
// Helpers (sm_80 ISA only — NO tcgen05/TMA; ptxas targets plain sm_100)
// ============================================================================
__device__ __forceinline__ uint32_t smem_u32(const void* p) {
    uint32_t a;
    asm("{ .reg .u64 t; cvta.to.shared.u64 t, %1; cvt.u32.u64 %0, t; }"
        : "=r"(a) : "l"(p));
    return a;
}

__device__ __forceinline__ void ldmatrix_x4(uint32_t& r0, uint32_t& r1,
                                            uint32_t& r2, uint32_t& r3,
                                            uint32_t addr) {
    asm volatile("ldmatrix.sync.aligned.m8n8.x4.shared.b16 {%0,%1,%2,%3}, [%4];"
                 : "=r"(r0), "=r"(r1), "=r"(r2), "=r"(r3) : "r"(addr));
}

__device__ __forceinline__ void mma_f16(float* c, uint32_t a0, uint32_t a1,
                                        uint32_t a2, uint32_t a3,
                                        uint32_t b0, uint32_t b1) {
    asm volatile(
        "mma.sync.aligned.m16n8k16.row.col.f32.f16.f16.f32 "
        "{%0,%1,%2,%3}, {%4,%5,%6,%7}, {%8,%9}, {%0,%1,%2,%3};"
        : "+f"(c[0]), "+f"(c[1]), "+f"(c[2]), "+f"(c[3])
        : "r"(a0), "r"(a1), "r"(a2), "r"(a3), "r"(b0), "r"(b1));
}

__device__ __forceinline__ void mma_s8(int* c, uint32_t a0, uint32_t a1,
                                       uint32_t a2, uint32_t a3,
                                       uint32_t b0, uint32_t b1) {
    asm volatile(
        "mma.sync.aligned.m16n8k32.row.col.s32.s8.s8.s32 "
        "{%0,%1,%2,%3}, {%4,%5,%6,%7}, {%8,%9}, {%0,%1,%2,%3};"
        : "+r"(c[0]), "+r"(c[1]), "+r"(c[2]), "+r"(c[3])
        : "r"(a0), "r"(a1), "r"(a2), "r"(a3), "r"(b0), "r"(b1));
}

__device__ __forceinline__ void cp_async16(uint32_t s, const void* g) {
    asm volatile("cp.async.cg.shared.global [%0], [%1], 16;" :: "r"(s), "l"(g));
}
#define CP_COMMIT() asm volatile("cp.async.commit_group;")
#define CP_WAIT(n)  asm volatile("cp.async.wait_group %0;" :: "n"(n))

__device__ __forceinline__ int q_s8(float v, float q) {
    int r = __float2int_rn(v * q);
    return min(127, max(-127, r));
}
__device__ __forceinline__ uint32_t pack4_s8(int a, int b, int c, int d) {
    return (uint32_t)(a & 255) | ((uint32_t)(b & 255) << 8) |
           ((uint32_t)(c & 255) << 16) | ((uint32_t)(d & 255) << 24);
}

// ============================================================================
// Fused softmax over rows of P0..P3 (+ amax reset). blockIdx.y selects matrix.
// P0 -> fp32 transposed (S0t); P1..P3 -> fp16 row-major.
// ============================================================================
__global__ void softmax4(const float* __restrict__ P0, const float* __restrict__ P1,
                         const float* __restrict__ P2, const float* __restrict__ P3,
                         float* __restrict__ S0t, __half* __restrict__ S1,
                         __half* __restrict__ S2, __half* __restrict__ S3) {
    if (blockIdx.x == 0 && blockIdx.y == 0 && threadIdx.x == 0)
        g_amax_bits = 0u;

    int which = blockIdx.y;
    const float* P = (which == 0) ? P0 : (which == 1) ? P1 : (which == 2) ? P2 : P3;
    __half* S16 = (which == 1) ? S1 : (which == 2) ? S2 : S3;

    int row = blockIdx.x;
    const float* p = P + (size_t)row * DDIM;
    int tid = threadIdx.x;  // 256
    __shared__ float red[8];

    float v[4];
    float mx = -3.4e38f;
#pragma unroll
    for (int j = 0; j < 4; j++) { v[j] = p[tid + j * 256]; mx = fmaxf(mx, v[j]); }
#pragma unroll
    for (int o = 16; o; o >>= 1) mx = fmaxf(mx, __shfl_xor_sync(0xffffffffu, mx, o));
    if ((tid & 31) == 0) red[tid >> 5] = mx;
    __syncthreads();
    mx = red[0];
#pragma unroll
    for (int i = 1; i < 8; i++) mx = fmaxf(mx, red[i]);
    __syncthreads();

    float sum = 0.f;
#pragma unroll
    for (int j = 0; j < 4; j++) { v[j] = expf(v[j] - mx); sum += v[j]; }
#pragma unroll
    for (int o = 16; o; o >>= 1) sum += __shfl_xor_sync(0xffffffffu, sum, o);
    if ((tid & 31) == 0) red[tid >> 5] = sum;
    __syncthreads();
    sum = 0.f;
#pragma unroll
    for (int i = 0; i < 8; i++) sum += red[i];
    float inv = 1.0f / sum;

#pragma unroll
    for (int j = 0; j < 4; j++) {
        int c = tid + j * 256;
        float val = v[j] * inv;
        if (which == 0) S0t[(size_t)c * DDIM + row] = val;
        else            S16[(size_t)row * DDIM + c] = __float2half_rn(val);
    }
}

// ============================================================================
// H[d][n*32+o] = sum_i G[d][n*32+i] * Kb[n][i][o]; fp32 in, fp16 out.
// ============================================================================
__global__ void blockdiag16(const float* __restrict__ G,
                            const float* __restrict__ Kb,
                            __half* __restrict__ H) {
    __shared__ float Ks[32][33];
    int n  = blockIdx.x;
    int d0 = blockIdx.y * 32;
    int t  = threadIdx.y * 32 + threadIdx.x;
    for (int idx = t; idx < 1024; idx += 256)
        Ks[idx >> 5][idx & 31] = Kb[n * 1024 + idx];
    __syncthreads();

    int lane = threadIdx.x;
    int w    = threadIdx.y;
    float kreg[32];
#pragma unroll
    for (int i = 0; i < 32; i++) kreg[i] = Ks[i][lane];

#pragma unroll
    for (int r = 0; r < 4; r++) {
        int d = d0 + w * 4 + r;
        float gv = G[(size_t)d * DDIM + n * 32 + lane];
        float s = 0.f;
#pragma unroll
        for (int i = 0; i < 32; i++)
            s += __shfl_sync(0xffffffffu, gv, i) * kreg[i];
        H[(size_t)d * DDIM + n * 32 + lane] = __float2half_rn(s);
    }
}

// ============================================================================
// x fp32 -> s8 (8 elems / thread), static scale 127/XCLIP
// ============================================================================
__global__ void convert_x_s8(const float4* __restrict__ in, uint2* __restrict__ out,
                             int n8) {
    int i = blockIdx.x * 256 + threadIdx.x;
    if (i >= n8) return;
    const float q = 127.0f / XCLIP;
    float4 v0 = in[2 * i], v1 = in[2 * i + 1];
    uint32_t lo = pack4_s8(q_s8(v0.x, q), q_s8(v0.y, q), q_s8(v0.z, q), q_s8(v0.w, q));
    uint32_t hi = pack4_s8(q_s8(v1.x, q), q_s8(v1.y, q), q_s8(v1.z, q), q_s8(v1.w, q));
    out[i] = make_uint2(lo, hi);
}

// ============================================================================
// M fp32 -> s8 with dynamic scale 127/amax
// ============================================================================
__global__ void convert_M_s8(const float* __restrict__ M, uint2* __restrict__ out) {
    int i = blockIdx.x * 256 + threadIdx.x;  // 1M/8 threads
    float amax = __uint_as_float(g_amax_bits);
    float q = (amax > 1e-30f) ? (127.0f / amax) : 0.f;
    const float4 v0 = reinterpret_cast<const float4*>(M)[2 * i];
    const float4 v1 = reinterpret_cast<const float4*>(M)[2 * i + 1];
    uint32_t lo = pack4_s8(q_s8(v0.x, q), q_s8(v0.y, q), q_s8(v0.z, q), q_s8(v0.w, q));
    uint32_t hi = pack4_s8(q_s8(v1.x, q), q_s8(v1.y, q), q_s8(v1.z, q), q_s8(v1.w, q));
    out[i] = make_uint2(lo, hi);
}

// ============================================================================
// Chain GEMM config: BM=32, BN=64, BK=32; 4 warps (2m x 2n), warp tile 16x32;
// cp.async 4-stage; grid (16,32) = 512 CTAs (one full wave, ~2x occupancy).
// ============================================================================
#define BKC       32
#define PADE      40
#define CHA16     (32 * PADE * 2)               // 2560 B (A: 32 rows)
#define CHB16     (64 * PADE * 2)               // 5120 B (B: 64 rows)
#define F16_STAGE (CHA16 + CHB16)               // 7680
#define F16_NSTAGE 4
#define F16_SMEM  (F16_NSTAGE * F16_STAGE)      // 30720

// Mainloop body shared by both chain kernels (acc[4][4] fp32, warp tile 16x32).
#define CHAIN_MAINLOOP()                                                       \
    const char* gptr[3];                                                       \
    uint32_t    soff[3];                                                       \
    {   /* A: 128 chunks of 16B */                                             \
        int c = tid;                                                           \
        int row = c >> 2, cc = c & 3;                                          \
        gptr[0] = reinterpret_cast<const char*>(A + (size_t)(m0 + row) * K + cc * 8); \
        soff[0] = (uint32_t)(row * (PADE * 2) + cc * 16);                      \
    }                                                                          \
    _Pragma("unroll")                                                          \
    for (int j = 0; j < 2; j++) {   /* B: 256 chunks */                        \
        int c = tid + j * 128;                                                 \
        int row = c >> 2, cc = c & 3;                                          \
        gptr[1 + j] = reinterpret_cast<const char*>(B + (size_t)(n0 + row) * K + cc * 8); \
        soff[1 + j] = (uint32_t)(CHA16 + row * (PADE * 2) + cc * 16);          \
    }                                                                          \
    auto issue_stage = [&](int st, int k0) {                                   \
        uint32_t sb = smem_base + (uint32_t)st * F16_STAGE;                    \
        _Pragma("unroll")                                                      \
        for (int j = 0; j < 3; j++)                                            \
            cp_async16(sb + soff[j], gptr[j] + (size_t)k0 * 2);                \
    };                                                                         \
    float acc[4][4];                                                           \
    _Pragma("unroll")                                                          \
    for (int j = 0; j < 4; j++)                                                \
        _Pragma("unroll")                                                      \
        for (int q = 0; q < 4; q++) acc[j][q] = 0.f;                           \
    int a_row  = wm + (lane & 15);                                             \
    int a_col8 = (lane >> 4) * 8;                                              \
    int b_row  = wn + (lane & 7) + ((lane >> 3) & 1) * 8;                      \
    int b_col8 = (lane >> 4) * 8;                                              \
    int nck = K / BKC;                                                         \
    _Pragma("unroll")                                                          \
    for (int s = 0; s < F16_NSTAGE - 1; s++) {                                 \
        issue_stage(s, s * BKC);                                               \
        CP_COMMIT();                                                           \
    }                                                                          \
    for (int ck = 0; ck < nck; ck++) {                                         \
        CP_WAIT(F16_NSTAGE - 2);                                               \
        __syncthreads();                                                       \
        int pf = ck + F16_NSTAGE - 1;                                          \
        if (pf < nck) issue_stage(pf & (F16_NSTAGE - 1), pf * BKC);            \
        CP_COMMIT();                                                           \
        uint32_t sb  = smem_base + (uint32_t)(ck & (F16_NSTAGE - 1)) * F16_STAGE; \
        uint32_t chA = sb;                                                     \
        uint32_t chB = sb + CHA16;                                             \
        _Pragma("unroll")                                                      \
        for (int kk = 0; kk < BKC; kk += 16) {                                 \
            uint32_t bfr[2][4];                                                \
            _Pragma("unroll")                                                  \
            for (int p = 0; p < 2; p++) {                                      \
                uint32_t off = ((b_row + p * 16) * PADE + kk + b_col8) * 2;    \
                ldmatrix_x4(bfr[p][0], bfr[p][1], bfr[p][2], bfr[p][3], chB + off); \
            }                                                                  \
            uint32_t offA = (a_row * PADE + kk + a_col8) * 2;                  \
            uint32_t a0, a1, a2, a3;                                           \
            ldmatrix_x4(a0, a1, a2, a3, chA + offA);                           \
            _Pragma("unroll")                                                  \
            for (int ni = 0; ni < 4; ni++) {                                   \
                int p = ni >> 1, s = ni & 1;                                   \
                mma_f16(acc[ni], a0, a1, a2, a3, bfr[p][s], bfr[p][2 + s]);    \
            }                                                                  \
        }                                                                      \
    }

// ----------------------------------------------------------------------------
// Chain GEMM + fused blockdiag epilogue: H = (A·B^T)·blockdiag(Kb), fp16 out.
// Each warp's 32-wide n-tile aligns with exactly one 32x32 K block.
// ----------------------------------------------------------------------------
__global__ void __launch_bounds__(128, 4)
gemm_bd_f16(const __half* __restrict__ A, const __half* __restrict__ B,
            const float* __restrict__ Kb, __half* __restrict__ H,
            int M, int N, int K) {
    extern __shared__ char smraw[];
    uint32_t smem_base = smem_u32(smraw);

    int tid  = threadIdx.x;
    int wid  = tid >> 5;
    int lane = tid & 31;
    int m0 = blockIdx.y * 32;
    int n0 = blockIdx.x * 64;
    int wm = (wid & 1) * 16;
    int wn = (wid >> 1) * 32;

    CHAIN_MAINLOOP();

    // ---- fused blockdiag epilogue ----
    __syncthreads();                      // all warps done with pipeline smem
    float* smf = reinterpret_cast<float*>(smraw);
    int b0 = n0 >> 5;                     // CTA covers K blocks b0, b0+1
    for (int idx = tid; idx < 2048; idx += 128) {
        int blk = idx >> 10;
        int rem = idx & 1023;
        int i   = rem >> 5;
        int o   = rem & 31;
        smf[blk * (32 * 33) + i * 33 + o] = Kb[(b0 + blk) * 1024 + i * 32 + o];
    }
    __syncthreads();

    int wb = wn >> 5;                     // which K block this warp uses
    float kreg[32];
#pragma unroll
    for (int i = 0; i < 32; i++) kreg[i] = smf[wb * (32 * 33) + i * 33 + lane];

    // stage this warp's 16x32 fp32 tile
    float* Cs = smf + 2 * (32 * 33) + wid * (16 * 33);
    int g   = lane >> 2;
    int tig = lane & 3;
#pragma unroll
    for (int ni = 0; ni < 4; ni++)
#pragma unroll
        for (int q = 0; q < 4; q++) {
            int rl = g + (q >> 1) * 8;
            int cl = ni * 8 + 2 * tig + (q & 1);
            Cs[rl * 33 + cl] = acc[ni][q];
        }
    __syncwarp();

#pragma unroll 4
    for (int r = 0; r < 16; r++) {
        float s = 0.f;
#pragma unroll
        for (int i = 0; i < 32; i++) s += Cs[r * 33 + i] * kreg[i];
        H[(size_t)(m0 + wm + r) * N + n0 + wn + lane] = __float2half_rn(s);
    }
}

// ----------------------------------------------------------------------------
// Plain chain GEMM: C = A·B^T, fp32 out, with amax atomicMax in epilogue.
// ----------------------------------------------------------------------------
__global__ void __launch_bounds__(128, 4)
gemm_tn_f16(const __half* __restrict__ A, const __half* __restrict__ B,
            float* __restrict__ C, int M, int N, int K) {
    extern __shared__ char smraw[];
    uint32_t smem_base = smem_u32(smraw);

    int tid  = threadIdx.x;
    int wid  = tid >> 5;
    int lane = tid & 31;
    int m0 = blockIdx.y * 32;
    int n0 = blockIdx.x * 64;
    int wm = (wid & 1) * 16;
    int wn = (wid >> 1) * 32;

    CHAIN_MAINLOOP();

    int g   = lane >> 2;
    int tig = lane & 3;
    float lmax = 0.f;
#pragma unroll
    for (int ni = 0; ni < 4; ni++) {
        int col = n0 + wn + ni * 8 + 2 * tig;
        int r0 = m0 + wm + g;
        *reinterpret_cast<float2*>(C + (size_t)r0 * N + col) =
            make_float2(acc[ni][0], acc[ni][1]);
        *reinterpret_cast<float2*>(C + (size_t)(r0 + 8) * N + col) =
            make_float2(acc[ni][2], acc[ni][3]);
#pragma unroll
        for (int q = 0; q < 4; q++) lmax = fmaxf(lmax, fabsf(acc[ni][q]));
    }
#pragma unroll
    for (int o = 16; o; o >>= 1)
        lmax = fmaxf(lmax, __shfl_xor_sync(0xffffffffu, lmax, o));
    if (lane == 0) atomicMax(&g_amax_bits, __float_as_uint(lmax));
}

// ============================================================================
// s8 single-pass TN GEMM (big GEMM): C = (A*B^T)*scale + bias, fp32 out.
// BM=128, BN=256, BK=128 bytes; 16 warps (4m x 4n), warp tile 32x64;
// m16n8k32 s8 IMMA; cp.async 3-stage ring; 1 CTA/SM.
// ============================================================================
#define Q_PAD    144                            // bytes per smem row (128+16)
#define Q_CHA    (128 * Q_PAD)                  // 18432
#define Q_CHB    (256 * Q_PAD)                  // 36864
#define Q_STAGE  (Q_CHA + Q_CHB)                // 55296
#define Q_NST    3
#define Q_SMEM   (Q_NST * Q_STAGE)              // 165888
#define Q_BK     128

__global__ void __launch_bounds__(512, 1)
gemm_tn_s8(const int8_t* __restrict__ A, const int8_t* __restrict__ B,
           float* __restrict__ C, int M, int N, int K,
           const float* __restrict__ bias) {
    extern __shared__ char smraw[];
    uint32_t smem_base = smem_u32(smraw);

    int tid  = threadIdx.x;
    int wid  = tid >> 5;
    int lane = tid & 31;
    int m0 = blockIdx.y * 128;
    int n0 = blockIdx.x * 256;
    int wm = (wid & 3) * 32;       // 4 m-warps
    int wn = (wid >> 2) * 64;      // 4 n-warps

    uint32_t goff[6];
    uint32_t soff[6];
#pragma unroll
    for (int j = 0; j < 2; j++) {       // A
        int c = tid + j * 512;
        int row = c >> 3, cc = c & 7;
        goff[j] = (uint32_t)((m0 + row) * K + cc * 16);
        soff[j] = (uint32_t)(row * Q_PAD + cc * 16);
    }
#pragma unroll
    for (int j = 0; j < 4; j++) {       // B
        int c = tid + j * 512;
        int row = c >> 3, cc = c & 7;
        goff[2 + j] = (uint32_t)((n0 + row) * K + cc * 16);
        soff[2 + j] = (uint32_t)(Q_CHA + row * Q_PAD + cc * 16);
    }

    auto issue_stage = [&](int st, int k0) {
        uint32_t sb = smem_base + (uint32_t)st * Q_STAGE;
#pragma unroll
        for (int j = 0; j < 2; j++)
            cp_async16(sb + soff[j], A + goff[j] + k0);
#pragma unroll
        for (int j = 2; j < 6; j++)
            cp_async16(sb + soff[j], B + goff[j] + k0);
    };

    int acc[2][8][4];
#pragma unroll
    for (int i = 0; i < 2; i++)
#pragma unroll
        for (int j = 0; j < 8; j++)
#pragma unroll
            for (int q = 0; q < 4; q++) acc[i][j][q] = 0;

    int a_row  = wm + (lane & 15);
    int a_koff = (lane >> 4) * 16;
    int b_col  = wn + (lane & 7) + ((lane >> 4) & 1) * 8;
    int b_koff = ((lane >> 3) & 1) * 16;

    int nck = K / Q_BK;                 // 8
#pragma unroll
    for (int s = 0; s < Q_NST - 1; s++) {
        issue_stage(s, s * Q_BK);
        CP_COMMIT();
    }

    int st_c = 0, st_p = Q_NST - 1;
    for (int ck = 0; ck < nck; ck++) {
        CP_WAIT(Q_NST - 2);
        __syncthreads();

        int pf = ck + Q_NST - 1;
        if (pf < nck) issue_stage(st_p, pf * Q_BK);
        CP_COMMIT();
        if (++st_p == Q_NST) st_p = 0;

        uint32_t sb  = smem_base + (uint32_t)st_c * Q_STAGE;
        if (++st_c == Q_NST) st_c = 0;
        uint32_t chA = sb;
        uint32_t chB = sb + Q_CHA;

#pragma unroll
        for (int ks = 0; ks < 4; ks++) {       // four k32 steps cover 128B
            uint32_t bfr[4][4];
#pragma unroll
            for (int p = 0; p < 4; p++) {
                uint32_t off = (b_col + p * 16) * Q_PAD + ks * 32 + b_koff;
                ldmatrix_x4(bfr[p][0], bfr[p][1], bfr[p][2], bfr[p][3], chB + off);
            }
#pragma unroll
            for (int mi = 0; mi < 2; mi++) {
                uint32_t offA = (a_row + mi * 16) * Q_PAD + ks * 32 + a_koff;
                uint32_t a0, a1, a2, a3;
                ldmatrix_x4(a0, a1, a2, a3, chA + offA);
#pragma unroll
                for (int ni = 0; ni < 8; ni++) {
                    int p = ni >> 1, s = ni & 1;
                    mma_s8(acc[mi][ni], a0, a1, a2, a3,
                           bfr[p][s * 2], bfr[p][s * 2 + 1]);
                }
            }
        }
    }

    // dequant scale: (XCLIP/127) * (amax/127)
    float amax = __uint_as_float(g_amax_bits);
    float sxm = (XCLIP / 127.0f) * (amax / 127.0f);

    int g   = lane >> 2;
    int tig = lane & 3;
#pragma unroll
    for (int mi = 0; mi < 2; mi++) {
#pragma unroll
        for (int ni = 0; ni < 8; ni++) {
            int col = n0 + wn + ni * 8 + 2 * tig;
            float bx = bias[col], by = bias[col + 1];
            int r0 = m0 + wm + mi * 16 + g;
            *reinterpret_cast<float2*>(C + (size_t)r0 * N + col) =
                make_float2((float)acc[mi][ni][0] * sxm + bx,
                            (float)acc[mi][ni][1] * sxm + by);
            *reinterpret_cast<float2*>(C + (size_t)(r0 + 8) * N + col) =
                make_float2((float)acc[mi][ni][2] * sxm + bx,
                            (float)acc[mi][ni][3] * sxm + by);
        }
    }
}

// ============================================================================
// Launch
// ============================================================================
extern "C" void kernel_launch(void* const* d_in, const int* in_sizes, int n_in,
                              void* d_out, int out_size) {
    const float* x    = (const float*)d_in[0];
    const float* P0   = (const float*)d_in[1];
    const float* P1   = (const float*)d_in[2];
    const float* P2   = (const float*)d_in[3];
    const float* P3   = (const float*)d_in[4];
    const float* K0   = (const float*)d_in[5];
    const float* K1   = (const float*)d_in[6];
    const float* K2   = (const float*)d_in[7];
    const float* bias = (const float*)d_in[8];
    float* out = (float*)d_out;

    (void)in_sizes; (void)n_in; (void)out_size;

    cudaFuncSetAttribute(gemm_bd_f16,
                         cudaFuncAttributeMaxDynamicSharedMemorySize, F16_SMEM);
    cudaFuncSetAttribute(gemm_tn_f16,
                         cudaFuncAttributeMaxDynamicSharedMemorySize, F16_SMEM);
    cudaFuncSetAttribute(gemm_tn_s8,
                         cudaFuncAttributeMaxDynamicSharedMemorySize, Q_SMEM);

    float *S0t, *Mm;
    __half *S1, *S2, *S3, *T0a, *T0b;
    int8_t *M8, *x8;
    cudaGetSymbolAddress((void**)&S0t, g_S0t);
    cudaGetSymbolAddress((void**)&Mm,  g_M);
    cudaGetSymbolAddress((void**)&S1,  g_S1);
    cudaGetSymbolAddress((void**)&S2,  g_S2);
    cudaGetSymbolAddress((void**)&S3,  g_S3);
    cudaGetSymbolAddress((void**)&T0a, g_T0a);
    cudaGetSymbolAddress((void**)&T0b, g_T0b);
    cudaGetSymbolAddress((void**)&M8,  g_M8);
    cudaGetSymbolAddress((void**)&x8,  g_x8);

    dim3 bdGrid(32, DDIM / 32), bdBlk(32, 8);
    dim3 gSmall(DDIM / 64, DDIM / 32);    // (16, 32) = 512 CTAs

    // 1) Fused softmaxes (+amax reset): P0 -> fp32 transposed; P1..P3 -> fp16
    softmax4<<<dim3(DDIM, 4), 256>>>(P0, P1, P2, P3, S0t, S1, S2, S3);

    // 2) Compose W^T (kept transposed; blockdiags fused into GEMM epilogues):
    blockdiag16<<<bdGrid, bdBlk>>>(S0t, K0, T0a);                               // G1
    gemm_bd_f16<<<gSmall, 128, F16_SMEM>>>(T0a, S1, K1, T0b, DDIM, DDIM, DDIM); // G2·Bd1 = G3
    gemm_bd_f16<<<gSmall, 128, F16_SMEM>>>(T0b, S2, K2, T0a, DDIM, DDIM, DDIM); // G4·Bd2 = G5
    gemm_tn_f16<<<gSmall, 128, F16_SMEM>>>(S3, T0a, Mm, DDIM, DDIM, DDIM);      // M (+amax)

    // 3) Quantize M (dynamic scale) and x (static clip scale) to s8
    convert_M_s8<<<(DDIM * DDIM / 8) / 256, 256>>>(Mm, (uint2*)M8);
    int n8 = (BDIM * DDIM) / 8;
    convert_x_s8<<<n8 / 256, 256>>>((const float4*)x, (uint2*)x8, n8);

    // 4) out[b][u] = sum_d x[b][d]·M[u][d] + bias[u]  (s8 IMMA, exact int acc)
    dim3 gBig(DDIM / 256, BDIM / 128);    // (4, 256) = 1024 CTAs
    gemm_tn_s8<<<gBig, 512, Q_SMEM>>>(x8, M8, out, BDIM, DDIM, DDIM, bias);
}

// round 16
// speedup vs baseline: 1.0446x; 1.0446x over previous
#include <cuda_runtime.h>
#include <cuda_fp16.h>
#include <cstdint>

// ============================================================================
// Problem constants
// ============================================================================
#define BDIM   32768
#define DDIM   1024
#define XCLIP  7.0f                   // |x| clip for s8 quant (P(|x|>7)~1e-12)

// ============================================================================
// Scratch (device globals — no runtime allocation allowed)
// ============================================================================
__device__ float g_S0t[DDIM * DDIM];          // softmax(P0)^T fp32
__device__ __half g_S1[DDIM * DDIM];
__device__ __half g_S2[DDIM * DDIM];
__device__ __half g_S3[DDIM * DDIM];
__device__ __half g_T0a[DDIM * DDIM];
__device__ __half g_T0b[DDIM * DDIM];
__device__ int8_t g_M8[DDIM * DDIM];          // s8(M * 127/amax(T0a))
__device__ int8_t g_x8[(size_t)BDIM * DDIM];  // s8(x * 127/XCLIP)
__device__ unsigned g_amax_bits;              // bits of amax(|T0a|) >= amax(|M|)

// ============================================================================
// Helpers (sm_80 ISA only — NO tcgen05/TMA; ptxas targets plain sm_100)
// ============================================================================
__device__ __forceinline__ uint32_t smem_u32(const void* p) {
    uint32_t a;
    asm("{ .reg .u64 t; cvta.to.shared.u64 t, %1; cvt.u32.u64 %0, t; }"
        : "=r"(a) : "l"(p));
    return a;
}

__device__ __forceinline__ void ldmatrix_x4(uint32_t& r0, uint32_t& r1,
                                            uint32_t& r2, uint32_t& r3,
                                            uint32_t addr) {
    asm volatile("ldmatrix.sync.aligned.m8n8.x4.shared.b16 {%0,%1,%2,%3}, [%4];"
                 : "=r"(r0), "=r"(r1), "=r"(r2), "=r"(r3) : "r"(addr));
}

__device__ __forceinline__ void mma_f16(float* c, uint32_t a0, uint32_t a1,
                                        uint32_t a2, uint32_t a3,
                                        uint32_t b0, uint32_t b1) {
    asm volatile(
        "mma.sync.aligned.m16n8k16.row.col.f32.f16.f16.f32 "
        "{%0,%1,%2,%3}, {%4,%5,%6,%7}, {%8,%9}, {%0,%1,%2,%3};"
        : "+f"(c[0]), "+f"(c[1]), "+f"(c[2]), "+f"(c[3])
        : "r"(a0), "r"(a1), "r"(a2), "r"(a3), "r"(b0), "r"(b1));
}

__device__ __forceinline__ void mma_s8(int* c, uint32_t a0, uint32_t a1,
                                       uint32_t a2, uint32_t a3,
                                       uint32_t b0, uint32_t b1) {
    asm volatile(
        "mma.sync.aligned.m16n8k32.row.col.s32.s8.s8.s32 "
        "{%0,%1,%2,%3}, {%4,%5,%6,%7}, {%8,%9}, {%0,%1,%2,%3};"
        : "+r"(c[0]), "+r"(c[1]), "+r"(c[2]), "+r"(c[3])
        : "r"(a0), "r"(a1), "r"(a2), "r"(a3), "r"(b0), "r"(b1));
}

__device__ __forceinline__ void cp_async16(uint32_t s, const void* g) {
    asm volatile("cp.async.cg.shared.global [%0], [%1], 16;" :: "r"(s), "l"(g));
}
#define CP_COMMIT() asm volatile("cp.async.commit_group;")
#define CP_WAIT(n)  asm volatile("cp.async.wait_group %0;" :: "n"(n))

__device__ __forceinline__ int q_s8(float v, float q) {
    int r = __float2int_rn(v * q);
    return min(127, max(-127, r));
}
__device__ __forceinline__ uint32_t pack4_s8(int a, int b, int c, int d) {
    return (uint32_t)(a & 255) | ((uint32_t)(b & 255) << 8) |
           ((uint32_t)(c & 255) << 16) | ((uint32_t)(d & 255) << 24);
}

// ============================================================================
// Fused softmax over rows of P0..P3 (+ amax reset). blockIdx.y selects matrix.
// P0 -> fp32 transposed (S0t); P1..P3 -> fp16 row-major.
// ============================================================================
__global__ void softmax4(const float* __restrict__ P0, const float* __restrict__ P1,
                         const float* __restrict__ P2, const float* __restrict__ P3,
                         float* __restrict__ S0t, __half* __restrict__ S1,
                         __half* __restrict__ S2, __half* __restrict__ S3) {
    if (blockIdx.x == 0 && blockIdx.y == 0 && threadIdx.x == 0)
        g_amax_bits = 0u;

    int which = blockIdx.y;
    const float* P = (which == 0) ? P0 : (which == 1) ? P1 : (which == 2) ? P2 : P3;
    __half* S16 = (which == 1) ? S1 : (which == 2) ? S2 : S3;

    int row = blockIdx.x;
    const float* p = P + (size_t)row * DDIM;
    int tid = threadIdx.x;  // 256
    __shared__ float red[8];

    float v[4];
    float mx = -3.4e38f;
#pragma unroll
    for (int j = 0; j < 4; j++) { v[j] = p[tid + j * 256]; mx = fmaxf(mx, v[j]); }
#pragma unroll
    for (int o = 16; o; o >>= 1) mx = fmaxf(mx, __shfl_xor_sync(0xffffffffu, mx, o));
    if ((tid & 31) == 0) red[tid >> 5] = mx;
    __syncthreads();
    mx = red[0];
#pragma unroll
    for (int i = 1; i < 8; i++) mx = fmaxf(mx, red[i]);
    __syncthreads();

    float sum = 0.f;
#pragma unroll
    for (int j = 0; j < 4; j++) { v[j] = expf(v[j] - mx); sum += v[j]; }
#pragma unroll
    for (int o = 16; o; o >>= 1) sum += __shfl_xor_sync(0xffffffffu, sum, o);
    if ((tid & 31) == 0) red[tid >> 5] = sum;
    __syncthreads();
    sum = 0.f;
#pragma unroll
    for (int i = 0; i < 8; i++) sum += red[i];
    float inv = 1.0f / sum;

#pragma unroll
    for (int j = 0; j < 4; j++) {
        int c = tid + j * 256;
        float val = v[j] * inv;
        if (which == 0) S0t[(size_t)c * DDIM + row] = val;
        else            S16[(size_t)row * DDIM + c] = __float2half_rn(val);
    }
}

// ============================================================================
// H[d][n*32+o] = sum_i G[d][n*32+i] * Kb[n][i][o]; fp32 in, fp16 out.
// ============================================================================
__global__ void blockdiag16(const float* __restrict__ G,
                            const float* __restrict__ Kb,
                            __half* __restrict__ H) {
    __shared__ float Ks[32][33];
    int n  = blockIdx.x;
    int d0 = blockIdx.y * 32;
    int t  = threadIdx.y * 32 + threadIdx.x;
    for (int idx = t; idx < 1024; idx += 256)
        Ks[idx >> 5][idx & 31] = Kb[n * 1024 + idx];
    __syncthreads();

    int lane = threadIdx.x;
    int w    = threadIdx.y;
    float kreg[32];
#pragma unroll
    for (int i = 0; i < 32; i++) kreg[i] = Ks[i][lane];

#pragma unroll
    for (int r = 0; r < 4; r++) {
        int d = d0 + w * 4 + r;
        float gv = G[(size_t)d * DDIM + n * 32 + lane];
        float s = 0.f;
#pragma unroll
        for (int i = 0; i < 32; i++)
            s += __shfl_sync(0xffffffffu, gv, i) * kreg[i];
        H[(size_t)d * DDIM + n * 32 + lane] = __float2half_rn(s);
    }
}

// ============================================================================
// x fp32 -> s8 (8 elems / thread), static scale 127/XCLIP
// ============================================================================
__global__ void convert_x_s8(const float4* __restrict__ in, uint2* __restrict__ out,
                             int n8) {
    int i = blockIdx.x * 256 + threadIdx.x;
    if (i >= n8) return;
    const float q = 127.0f / XCLIP;
    float4 v0 = in[2 * i], v1 = in[2 * i + 1];
    uint32_t lo = pack4_s8(q_s8(v0.x, q), q_s8(v0.y, q), q_s8(v0.z, q), q_s8(v0.w, q));
    uint32_t hi = pack4_s8(q_s8(v1.x, q), q_s8(v1.y, q), q_s8(v1.z, q), q_s8(v1.w, q));
    out[i] = make_uint2(lo, hi);
}

// ============================================================================
// Chain GEMM config: BM=BN=64, BK=64; 4 warps (2x2), warp tile 32x32;
// cp.async 4-stage; grid (16,16)=256 CTAs; 16 K-iterations (half the syncs).
// ============================================================================
#define BKC       64
#define PADEC     72                            // fp16 elems/row (144B; banks r*9%8 distinct)
#define CHAC      (64 * PADEC * 2)              // 9216 B per operand per stage
#define F16_STAGE (2 * CHAC)                    // 18432
#define F16_NSTAGE 4
#define F16_SMEM  (F16_NSTAGE * F16_STAGE)      // 73728

// Mainloop (acc[2][4][4] fp32, warp tile 32x32, K in fp16 elems).
#define CHAIN_MAINLOOP()                                                       \
    const char* gptr[8];                                                       \
    uint32_t    soff[8];                                                       \
    _Pragma("unroll")                                                          \
    for (int j = 0; j < 4; j++) {   /* A: 512 chunks of 16B */                 \
        int c = tid + j * 128;                                                 \
        int row = c >> 3, cc = c & 7;                                          \
        gptr[j] = reinterpret_cast<const char*>(A + (size_t)(m0 + row) * K + cc * 8); \
        soff[j] = (uint32_t)(row * (PADEC * 2) + cc * 16);                     \
    }                                                                          \
    _Pragma("unroll")                                                          \
    for (int j = 0; j < 4; j++) {   /* B: 512 chunks */                        \
        int c = tid + j * 128;                                                 \
        int row = c >> 3, cc = c & 7;                                          \
        gptr[4 + j] = reinterpret_cast<const char*>(B + (size_t)(n0 + row) * K + cc * 8); \
        soff[4 + j] = (uint32_t)(CHAC + row * (PADEC * 2) + cc * 16);          \
    }                                                                          \
    auto issue_stage = [&](int st, int k0) {                                   \
        uint32_t sb = smem_base + (uint32_t)st * F16_STAGE;                    \
        _Pragma("unroll")                                                      \
        for (int j = 0; j < 8; j++)                                            \
            cp_async16(sb + soff[j], gptr[j] + (size_t)k0 * 2);                \
    };                                                                         \
    float acc[2][4][4];                                                        \
    _Pragma("unroll")                                                          \
    for (int i = 0; i < 2; i++)                                                \
        _Pragma("unroll")                                                      \
        for (int j = 0; j < 4; j++)                                            \
            _Pragma("unroll")                                                  \
            for (int q = 0; q < 4; q++) acc[i][j][q] = 0.f;                    \
    int a_row  = wm + (lane & 15);                                             \
    int a_col8 = (lane >> 4) * 8;                                              \
    int b_row  = wn + (lane & 7) + ((lane >> 3) & 1) * 8;                      \
    int b_col8 = (lane >> 4) * 8;                                              \
    int nck = K / BKC;                                                         \
    _Pragma("unroll")                                                          \
    for (int s = 0; s < F16_NSTAGE - 1; s++) {                                 \
        issue_stage(s, s * BKC);                                               \
        CP_COMMIT();                                                           \
    }                                                                          \
    for (int ck = 0; ck < nck; ck++) {                                         \
        CP_WAIT(F16_NSTAGE - 2);                                               \
        __syncthreads();                                                       \
        int pf = ck + F16_NSTAGE - 1;                                          \
        if (pf < nck) issue_stage(pf & (F16_NSTAGE - 1), pf * BKC);            \
        CP_COMMIT();                                                           \
        uint32_t sb  = smem_base + (uint32_t)(ck & (F16_NSTAGE - 1)) * F16_STAGE; \
        uint32_t chA = sb;                                                     \
        uint32_t chB = sb + CHAC;                                              \
        _Pragma("unroll")                                                      \
        for (int kk = 0; kk < BKC; kk += 16) {                                 \
            uint32_t bfr[2][4];                                                \
            _Pragma("unroll")                                                  \
            for (int p = 0; p < 2; p++) {                                      \
                uint32_t off = ((b_row + p * 16) * PADEC + kk + b_col8) * 2;   \
                ldmatrix_x4(bfr[p][0], bfr[p][1], bfr[p][2], bfr[p][3], chB + off); \
            }                                                                  \
            _Pragma("unroll")                                                  \
            for (int mi = 0; mi < 2; mi++) {                                   \
                uint32_t offA = ((a_row + mi * 16) * PADEC + kk + a_col8) * 2; \
                uint32_t a0, a1, a2, a3;                                       \
                ldmatrix_x4(a0, a1, a2, a3, chA + offA);                       \
                _Pragma("unroll")                                              \
                for (int ni = 0; ni < 4; ni++) {                               \
                    int p = ni >> 1, s = ni & 1;                               \
                    mma_f16(acc[mi][ni], a0, a1, a2, a3, bfr[p][s], bfr[p][2 + s]); \
                }                                                              \
            }                                                                  \
        }                                                                      \
    }

// ----------------------------------------------------------------------------
// Chain GEMM + fused blockdiag epilogue: H = (A·B^T)·blockdiag(Kb), fp16 out.
// do_amax: atomicMax of |H| into g_amax_bits (used on the LAST bd stage so the
// final quantizing GEMM has the bound amax(M) <= amax(T0a)).
// ----------------------------------------------------------------------------
__global__ void __launch_bounds__(128, 3)
gemm_bd_f16(const __half* __restrict__ A, const __half* __restrict__ B,
            const float* __restrict__ Kb, __half* __restrict__ H,
            int M, int N, int K, int do_amax) {
    extern __shared__ char smraw[];
    uint32_t smem_base = smem_u32(smraw);

    int tid  = threadIdx.x;
    int wid  = tid >> 5;
    int lane = tid & 31;
    int m0 = blockIdx.y * 64;
    int n0 = blockIdx.x * 64;
    int wm = (wid & 1) * 32;
    int wn = (wid >> 1) * 32;

    CHAIN_MAINLOOP();

    // ---- fused blockdiag epilogue ----
    __syncthreads();
    float* smf = reinterpret_cast<float*>(smraw);
    int b0 = n0 >> 5;
    for (int idx = tid; idx < 2048; idx += 128) {
        int blk = idx >> 10;
        int rem = idx & 1023;
        int i   = rem >> 5;
        int o   = rem & 31;
        smf[blk * (32 * 33) + i * 33 + o] = Kb[(b0 + blk) * 1024 + i * 32 + o];
    }
    __syncthreads();

    int wb = wn >> 5;
    float kreg[32];
#pragma unroll
    for (int i = 0; i < 32; i++) kreg[i] = smf[wb * (32 * 33) + i * 33 + lane];

    float* Cs = smf + 2 * (32 * 33) + wid * (32 * 33);
    int g   = lane >> 2;
    int tig = lane & 3;
#pragma unroll
    for (int mi = 0; mi < 2; mi++)
#pragma unroll
        for (int ni = 0; ni < 4; ni++)
#pragma unroll
            for (int q = 0; q < 4; q++) {
                int rl = mi * 16 + g + (q >> 1) * 8;
                int cl = ni * 8 + 2 * tig + (q & 1);
                Cs[rl * 33 + cl] = acc[mi][ni][q];
            }
    __syncwarp();

    float lmax = 0.f;
#pragma unroll 4
    for (int r = 0; r < 32; r++) {
        float s = 0.f;
#pragma unroll
        for (int i = 0; i < 32; i++) s += Cs[r * 33 + i] * kreg[i];
        lmax = fmaxf(lmax, fabsf(s));
        H[(size_t)(m0 + wm + r) * N + n0 + wn + lane] = __float2half_rn(s);
    }
    if (do_amax) {
#pragma unroll
        for (int o = 16; o; o >>= 1)
            lmax = fmaxf(lmax, __shfl_xor_sync(0xffffffffu, lmax, o));
        if (lane == 0) atomicMax(&g_amax_bits, __float_as_uint(lmax));
    }
}

// ----------------------------------------------------------------------------
// Final chain GEMM: M8 = s8( (A·B^T) * 127/amax ), amax = amax(T0a) bound.
// (amax(M) <= amax(T0a) because softmax rows are convex weights.)
// ----------------------------------------------------------------------------
__global__ void __launch_bounds__(128, 3)
gemm_q_f16(const __half* __restrict__ A, const __half* __restrict__ B,
           int8_t* __restrict__ C8, int M, int N, int K) {
    extern __shared__ char smraw[];
    uint32_t smem_base = smem_u32(smraw);

    int tid  = threadIdx.x;
    int wid  = tid >> 5;
    int lane = tid & 31;
    int m0 = blockIdx.y * 64;
    int n0 = blockIdx.x * 64;
    int wm = (wid & 1) * 32;
    int wn = (wid >> 1) * 32;

    CHAIN_MAINLOOP();

    float amax = __uint_as_float(g_amax_bits);
    float q = (amax > 1e-30f) ? (127.0f / amax) : 0.f;

    int g   = lane >> 2;
    int tig = lane & 3;
#pragma unroll
    for (int mi = 0; mi < 2; mi++) {
#pragma unroll
        for (int ni = 0; ni < 4; ni++) {
            int col = n0 + wn + ni * 8 + 2 * tig;
#pragma unroll
            for (int half = 0; half < 2; half++) {
                int r = m0 + wm + mi * 16 + g + half * 8;
                int v0 = q_s8(acc[mi][ni][half * 2 + 0], q);
                int v1 = q_s8(acc[mi][ni][half * 2 + 1], q);
                uint16_t pk = (uint16_t)((v0 & 255) | ((v1 & 255) << 8));
                *reinterpret_cast<uint16_t*>(C8 + (size_t)r * N + col) = pk;
            }
        }
    }
}

// ============================================================================
// s8 single-pass TN GEMM (big GEMM): C = (A*B^T)*scale + bias, fp32 out.
// BM=128, BN=256, BK=128 bytes; 16 warps (4m x 4n), warp tile 32x64;
// m16n8k32 s8 IMMA; cp.async 3-stage ring; 1 CTA/SM.
// ============================================================================
#define Q_PAD    144                            // bytes per smem row (128+16)
#define Q_CHA    (128 * Q_PAD)                  // 18432
#define Q_CHB    (256 * Q_PAD)                  // 36864
#define Q_STAGE  (Q_CHA + Q_CHB)                // 55296
#define Q_NST    3
#define Q_SMEM   (Q_NST * Q_STAGE)              // 165888
#define Q_BK     128

__global__ void __launch_bounds__(512, 1)
gemm_tn_s8(const int8_t* __restrict__ A, const int8_t* __restrict__ B,
           float* __restrict__ C, int M, int N, int K,
           const float* __restrict__ bias) {
    extern __shared__ char smraw[];
    uint32_t smem_base = smem_u32(smraw);

    int tid  = threadIdx.x;
    int wid  = tid >> 5;
    int lane = tid & 31;
    int m0 = blockIdx.y * 128;
    int n0 = blockIdx.x * 256;
    int wm = (wid & 3) * 32;       // 4 m-warps
    int wn = (wid >> 2) * 64;      // 4 n-warps

    uint32_t goff[6];
    uint32_t soff[6];
#pragma unroll
    for (int j = 0; j < 2; j++) {       // A
        int c = tid + j * 512;
        int row = c >> 3, cc = c & 7;
        goff[j] = (uint32_t)((m0 + row) * K + cc * 16);
        soff[j] = (uint32_t)(row * Q_PAD + cc * 16);
    }
#pragma unroll
    for (int j = 0; j < 4; j++) {       // B
        int c = tid + j * 512;
        int row = c >> 3, cc = c & 7;
        goff[2 + j] = (uint32_t)((n0 + row) * K + cc * 16);
        soff[2 + j] = (uint32_t)(Q_CHA + row * Q_PAD + cc * 16);
    }

    auto issue_stage = [&](int st, int k0) {
        uint32_t sb = smem_base + (uint32_t)st * Q_STAGE;
#pragma unroll
        for (int j = 0; j < 2; j++)
            cp_async16(sb + soff[j], A + goff[j] + k0);
#pragma unroll
        for (int j = 2; j < 6; j++)
            cp_async16(sb + soff[j], B + goff[j] + k0);
    };

    int acc[2][8][4];
#pragma unroll
    for (int i = 0; i < 2; i++)
#pragma unroll
        for (int j = 0; j < 8; j++)
#pragma unroll
            for (int q = 0; q < 4; q++) acc[i][j][q] = 0;

    int a_row  = wm + (lane & 15);
    int a_koff = (lane >> 4) * 16;
    int b_col  = wn + (lane & 7) + ((lane >> 4) & 1) * 8;
    int b_koff = ((lane >> 3) & 1) * 16;

    int nck = K / Q_BK;                 // 8
#pragma unroll
    for (int s = 0; s < Q_NST - 1; s++) {
        issue_stage(s, s * Q_BK);
        CP_COMMIT();
    }

    int st_c = 0, st_p = Q_NST - 1;
    for (int ck = 0; ck < nck; ck++) {
        CP_WAIT(Q_NST - 2);
        __syncthreads();

        int pf = ck + Q_NST - 1;
        if (pf < nck) issue_stage(st_p, pf * Q_BK);
        CP_COMMIT();
        if (++st_p == Q_NST) st_p = 0;

        uint32_t sb  = smem_base + (uint32_t)st_c * Q_STAGE;
        if (++st_c == Q_NST) st_c = 0;
        uint32_t chA = sb;
        uint32_t chB = sb + Q_CHA;

#pragma unroll
        for (int ks = 0; ks < 4; ks++) {       // four k32 steps cover 128B
            uint32_t bfr[4][4];
#pragma unroll
            for (int p = 0; p < 4; p++) {
                uint32_t off = (b_col + p * 16) * Q_PAD + ks * 32 + b_koff;
                ldmatrix_x4(bfr[p][0], bfr[p][1], bfr[p][2], bfr[p][3], chB + off);
            }
#pragma unroll
            for (int mi = 0; mi < 2; mi++) {
                uint32_t offA = (a_row + mi * 16) * Q_PAD + ks * 32 + a_koff;
                uint32_t a0, a1, a2, a3;
                ldmatrix_x4(a0, a1, a2, a3, chA + offA);
#pragma unroll
                for (int ni = 0; ni < 8; ni++) {
                    int p = ni >> 1, s = ni & 1;
                    mma_s8(acc[mi][ni], a0, a1, a2, a3,
                           bfr[p][s * 2], bfr[p][s * 2 + 1]);
                }
            }
        }
    }

    // dequant scale: (XCLIP/127) * (amax/127)
    float amax = __uint_as_float(g_amax_bits);
    float sxm = (XCLIP / 127.0f) * (amax / 127.0f);

    int g   = lane >> 2;
    int tig = lane & 3;
#pragma unroll
    for (int mi = 0; mi < 2; mi++) {
#pragma unroll
        for (int ni = 0; ni < 8; ni++) {
            int col = n0 + wn + ni * 8 + 2 * tig;
            float bx = bias[col], by = bias[col + 1];
            int r0 = m0 + wm + mi * 16 + g;
            *reinterpret_cast<float2*>(C + (size_t)r0 * N + col) =
                make_float2((float)acc[mi][ni][0] * sxm + bx,
                            (float)acc[mi][ni][1] * sxm + by);
            *reinterpret_cast<float2*>(C + (size_t)(r0 + 8) * N + col) =
                make_float2((float)acc[mi][ni][2] * sxm + bx,
                            (float)acc[mi][ni][3] * sxm + by);
        }
    }
}

// ============================================================================
// Launch
// ============================================================================
extern "C" void kernel_launch(void* const* d_in, const int* in_sizes, int n_in,
                              void* d_out, int out_size) {
    const float* x    = (const float*)d_in[0];
    const float* P0   = (const float*)d_in[1];
    const float* P1   = (const float*)d_in[2];
    const float* P2   = (const float*)d_in[3];
    const float* P3   = (const float*)d_in[4];
    const float* K0   = (const float*)d_in[5];
    const float* K1   = (const float*)d_in[6];
    const float* K2   = (const float*)d_in[7];
    const float* bias = (const float*)d_in[8];
    float* out = (float*)d_out;

    (void)in_sizes; (void)n_in; (void)out_size;

    cudaFuncSetAttribute(gemm_bd_f16,
                         cudaFuncAttributeMaxDynamicSharedMemorySize, F16_SMEM);
    cudaFuncSetAttribute(gemm_q_f16,
                         cudaFuncAttributeMaxDynamicSharedMemorySize, F16_SMEM);
    cudaFuncSetAttribute(gemm_tn_s8,
                         cudaFuncAttributeMaxDynamicSharedMemorySize, Q_SMEM);

    float *S0t;
    __half *S1, *S2, *S3, *T0a, *T0b;
    int8_t *M8, *x8;
    cudaGetSymbolAddress((void**)&S0t, g_S0t);
    cudaGetSymbolAddress((void**)&S1,  g_S1);
    cudaGetSymbolAddress((void**)&S2,  g_S2);
    cudaGetSymbolAddress((void**)&S3,  g_S3);
    cudaGetSymbolAddress((void**)&T0a, g_T0a);
    cudaGetSymbolAddress((void**)&T0b, g_T0b);
    cudaGetSymbolAddress((void**)&M8,  g_M8);
    cudaGetSymbolAddress((void**)&x8,  g_x8);

    dim3 bdGrid(32, DDIM / 32), bdBlk(32, 8);
    dim3 gSmall(DDIM / 64, DDIM / 64);    // (16, 16) = 256 CTAs

    // 1) Fused softmaxes (+amax reset): P0 -> fp32 transposed; P1..P3 -> fp16
    softmax4<<<dim3(DDIM, 4), 256>>>(P0, P1, P2, P3, S0t, S1, S2, S3);

    // 2) Compose W^T (blockdiags fused into GEMM epilogues); the last bd stage
    //    records amax(T0a) >= amax(M) (softmax rows are convex weights), so the
    //    final GEMM can quantize M to s8 directly.
    blockdiag16<<<bdGrid, bdBlk>>>(S0t, K0, T0a);                                  // G1
    gemm_bd_f16<<<gSmall, 128, F16_SMEM>>>(T0a, S1, K1, T0b, DDIM, DDIM, DDIM, 0); // G3
    gemm_bd_f16<<<gSmall, 128, F16_SMEM>>>(T0b, S2, K2, T0a, DDIM, DDIM, DDIM, 1); // G5 (+amax)
    gemm_q_f16<<<gSmall, 128, F16_SMEM>>>(S3, T0a, M8, DDIM, DDIM, DDIM);          // M8 s8

    // 3) Quantize x (static clip scale) to s8
    int n8 = (BDIM * DDIM) / 8;
    convert_x_s8<<<n8 / 256, 256>>>((const float4*)x, (uint2*)x8, n8);

    // 4) out[b][u] = sum_d x[b][d]·M[u][d] + bias[u]  (s8 IMMA, exact int acc)
    dim3 gBig(DDIM / 256, BDIM / 128);    // (4, 256) = 1024 CTAs
    gemm_tn_s8<<<gBig, 512, Q_SMEM>>>(x8, M8, out, BDIM, DDIM, DDIM, bias);
}

// round 17
// speedup vs baseline: 1.0635x; 1.0180x over previous
#include <cuda_runtime.h>
#include <cuda_fp16.h>
#include <cstdint>

// ============================================================================
// Problem constants
// ============================================================================
#define BDIM   32768
#define DDIM   1024
#define XCLIP  7.0f                   // |x| clip for s8 quant (P(|x|>7)~1e-12)

// ============================================================================
// Scratch (device globals — no runtime allocation allowed)
// ============================================================================
__device__ float g_S0t[DDIM * DDIM];          // softmax(P0)^T fp32
__device__ __half g_S1[DDIM * DDIM];
__device__ __half g_S2[DDIM * DDIM];
__device__ __half g_S3[DDIM * DDIM];
__device__ __half g_T0a[DDIM * DDIM];
__device__ __half g_T0b[DDIM * DDIM];
__device__ int8_t g_M8[DDIM * DDIM];          // s8(M * 127/amax(T0a))
__device__ int8_t g_x8[(size_t)BDIM * DDIM];  // s8(x * 127/XCLIP)
__device__ unsigned g_amax_bits;              // bits of amax(|T0a|) >= amax(|M|)

// ============================================================================
// Helpers (sm_80 ISA only — NO tcgen05/TMA; ptxas targets plain sm_100)
// ============================================================================
__device__ __forceinline__ uint32_t smem_u32(const void* p) {
    uint32_t a;
    asm("{ .reg .u64 t; cvta.to.shared.u64 t, %1; cvt.u32.u64 %0, t; }"
        : "=r"(a) : "l"(p));
    return a;
}

__device__ __forceinline__ void ldmatrix_x4(uint32_t& r0, uint32_t& r1,
                                            uint32_t& r2, uint32_t& r3,
                                            uint32_t addr) {
    asm volatile("ldmatrix.sync.aligned.m8n8.x4.shared.b16 {%0,%1,%2,%3}, [%4];"
                 : "=r"(r0), "=r"(r1), "=r"(r2), "=r"(r3) : "r"(addr));
}

__device__ __forceinline__ void mma_f16(float* c, uint32_t a0, uint32_t a1,
                                        uint32_t a2, uint32_t a3,
                                        uint32_t b0, uint32_t b1) {
    asm volatile(
        "mma.sync.aligned.m16n8k16.row.col.f32.f16.f16.f32 "
        "{%0,%1,%2,%3}, {%4,%5,%6,%7}, {%8,%9}, {%0,%1,%2,%3};"
        : "+f"(c[0]), "+f"(c[1]), "+f"(c[2]), "+f"(c[3])
        : "r"(a0), "r"(a1), "r"(a2), "r"(a3), "r"(b0), "r"(b1));
}

__device__ __forceinline__ void mma_s8(int* c, uint32_t a0, uint32_t a1,
                                       uint32_t a2, uint32_t a3,
                                       uint32_t b0, uint32_t b1) {
    asm volatile(
        "mma.sync.aligned.m16n8k32.row.col.s32.s8.s8.s32 "
        "{%0,%1,%2,%3}, {%4,%5,%6,%7}, {%8,%9}, {%0,%1,%2,%3};"
        : "+r"(c[0]), "+r"(c[1]), "+r"(c[2]), "+r"(c[3])
        : "r"(a0), "r"(a1), "r"(a2), "r"(a3), "r"(b0), "r"(b1));
}

__device__ __forceinline__ void cp_async16(uint32_t s, const void* g) {
    asm volatile("cp.async.cg.shared.global [%0], [%1], 16;" :: "r"(s), "l"(g));
}
#define CP_COMMIT() asm volatile("cp.async.commit_group;")
#define CP_WAIT(n)  asm volatile("cp.async.wait_group %0;" :: "n"(n))

__device__ __forceinline__ int q_s8(float v, float q) {
    int r = __float2int_rn(v * q);
    return min(127, max(-127, r));
}
__device__ __forceinline__ uint32_t pack4_s8(int a, int b, int c, int d) {
    return (uint32_t)(a & 255) | ((uint32_t)(b & 255) << 8) |
           ((uint32_t)(c & 255) << 16) | ((uint32_t)(d & 255) << 24);
}

// ============================================================================
// Fused softmax over rows of P0..P3 (+ amax reset). blockIdx.y selects matrix.
// P0 -> fp32 transposed (S0t); P1..P3 -> fp16 row-major.
// ============================================================================
__global__ void softmax4(const float* __restrict__ P0, const float* __restrict__ P1,
                         const float* __restrict__ P2, const float* __restrict__ P3,
                         float* __restrict__ S0t, __half* __restrict__ S1,
                         __half* __restrict__ S2, __half* __restrict__ S3) {
    if (blockIdx.x == 0 && blockIdx.y == 0 && threadIdx.x == 0)
        g_amax_bits = 0u;

    int which = blockIdx.y;
    const float* P = (which == 0) ? P0 : (which == 1) ? P1 : (which == 2) ? P2 : P3;
    __half* S16 = (which == 1) ? S1 : (which == 2) ? S2 : S3;

    int row = blockIdx.x;
    const float* p = P + (size_t)row * DDIM;
    int tid = threadIdx.x;  // 256
    __shared__ float red[8];

    float v[4];
    float mx = -3.4e38f;
#pragma unroll
    for (int j = 0; j < 4; j++) { v[j] = p[tid + j * 256]; mx = fmaxf(mx, v[j]); }
#pragma unroll
    for (int o = 16; o; o >>= 1) mx = fmaxf(mx, __shfl_xor_sync(0xffffffffu, mx, o));
    if ((tid & 31) == 0) red[tid >> 5] = mx;
    __syncthreads();
    mx = red[0];
#pragma unroll
    for (int i = 1; i < 8; i++) mx = fmaxf(mx, red[i]);
    __syncthreads();

    float sum = 0.f;
#pragma unroll
    for (int j = 0; j < 4; j++) { v[j] = expf(v[j] - mx); sum += v[j]; }
#pragma unroll
    for (int o = 16; o; o >>= 1) sum += __shfl_xor_sync(0xffffffffu, sum, o);
    if ((tid & 31) == 0) red[tid >> 5] = sum;
    __syncthreads();
    sum = 0.f;
#pragma unroll
    for (int i = 0; i < 8; i++) sum += red[i];
    float inv = 1.0f / sum;

#pragma unroll
    for (int j = 0; j < 4; j++) {
        int c = tid + j * 256;
        float val = v[j] * inv;
        if (which == 0) S0t[(size_t)c * DDIM + row] = val;
        else            S16[(size_t)row * DDIM + c] = __float2half_rn(val);
    }
}

// ============================================================================
// H[d][n*32+o] = sum_i G[d][n*32+i] * Kb[n][i][o]; fp32 in, fp16 out.
// ============================================================================
__global__ void blockdiag16(const float* __restrict__ G,
                            const float* __restrict__ Kb,
                            __half* __restrict__ H) {
    __shared__ float Ks[32][33];
    int n  = blockIdx.x;
    int d0 = blockIdx.y * 32;
    int t  = threadIdx.y * 32 + threadIdx.x;
    for (int idx = t; idx < 1024; idx += 256)
        Ks[idx >> 5][idx & 31] = Kb[n * 1024 + idx];
    __syncthreads();

    int lane = threadIdx.x;
    int w    = threadIdx.y;
    float kreg[32];
#pragma unroll
    for (int i = 0; i < 32; i++) kreg[i] = Ks[i][lane];

#pragma unroll
    for (int r = 0; r < 4; r++) {
        int d = d0 + w * 4 + r;
        float gv = G[(size_t)d * DDIM + n * 32 + lane];
        float s = 0.f;
#pragma unroll
        for (int i = 0; i < 32; i++)
            s += __shfl_sync(0xffffffffu, gv, i) * kreg[i];
        H[(size_t)d * DDIM + n * 32 + lane] = __float2half_rn(s);
    }
}

// ============================================================================
// x fp32 -> s8 (8 elems / thread), static scale 127/XCLIP
// ============================================================================
__global__ void convert_x_s8(const float4* __restrict__ in, uint2* __restrict__ out,
                             int n8) {
    int i = blockIdx.x * 256 + threadIdx.x;
    if (i >= n8) return;
    const float q = 127.0f / XCLIP;
    float4 v0 = in[2 * i], v1 = in[2 * i + 1];
    uint32_t lo = pack4_s8(q_s8(v0.x, q), q_s8(v0.y, q), q_s8(v0.z, q), q_s8(v0.w, q));
    uint32_t hi = pack4_s8(q_s8(v1.x, q), q_s8(v1.y, q), q_s8(v1.z, q), q_s8(v1.w, q));
    out[i] = make_uint2(lo, hi);
}

// ============================================================================
// Chain GEMM config: BM=BN=64, BK=64; 256 threads, 8 warps with split-K:
// warps 0-3 handle k-low-half of each stage, warps 4-7 k-high-half; warp tile
// 32x32. Merge partials via smem before epilogue. grid (16,16)=256 CTAs.
// ============================================================================
#define BKC       64
#define PADEC     72                            // fp16 elems/row (144B)
#define CHAC      (64 * PADEC * 2)              // 9216 B per operand per stage
#define F16_STAGE (2 * CHAC)                    // 18432
#define F16_NSTAGE 4
#define F16_SMEM  (F16_NSTAGE * F16_STAGE)      // 73728

// Mainloop: acc[2][4][4] fp32 partial for this warp's k-half.
// Defines: tid, wid, lane, kw (k-half), wsub, wm, wn, m0, n0 expected.
#define CHAIN_MAINLOOP()                                                       \
    const char* gptr[4];                                                       \
    uint32_t    soff[4];                                                       \
    _Pragma("unroll")                                                          \
    for (int j = 0; j < 2; j++) {   /* A: 512 chunks of 16B */                 \
        int c = tid + j * 256;                                                 \
        int row = c >> 3, cc = c & 7;                                          \
        gptr[j] = reinterpret_cast<const char*>(A + (size_t)(m0 + row) * K + cc * 8); \
        soff[j] = (uint32_t)(row * (PADEC * 2) + cc * 16);                     \
    }                                                                          \
    _Pragma("unroll")                                                          \
    for (int j = 0; j < 2; j++) {   /* B: 512 chunks */                        \
        int c = tid + j * 256;                                                 \
        int row = c >> 3, cc = c & 7;                                          \
        gptr[2 + j] = reinterpret_cast<const char*>(B + (size_t)(n0 + row) * K + cc * 8); \
        soff[2 + j] = (uint32_t)(CHAC + row * (PADEC * 2) + cc * 16);          \
    }                                                                          \
    auto issue_stage = [&](int st, int k0) {                                   \
        uint32_t sb = smem_base + (uint32_t)st * F16_STAGE;                    \
        _Pragma("unroll")                                                      \
        for (int j = 0; j < 4; j++)                                            \
            cp_async16(sb + soff[j], gptr[j] + (size_t)k0 * 2);                \
    };                                                                         \
    float acc[2][4][4];                                                        \
    _Pragma("unroll")                                                          \
    for (int i = 0; i < 2; i++)                                                \
        _Pragma("unroll")                                                      \
        for (int j = 0; j < 4; j++)                                            \
            _Pragma("unroll")                                                  \
            for (int q = 0; q < 4; q++) acc[i][j][q] = 0.f;                    \
    int a_row  = wm + (lane & 15);                                             \
    int a_col8 = (lane >> 4) * 8;                                              \
    int b_row  = wn + (lane & 7) + ((lane >> 3) & 1) * 8;                      \
    int b_col8 = (lane >> 4) * 8;                                              \
    int kbase  = kw * 32;                                                      \
    int nck = K / BKC;                                                         \
    _Pragma("unroll")                                                          \
    for (int s = 0; s < F16_NSTAGE - 1; s++) {                                 \
        issue_stage(s, s * BKC);                                               \
        CP_COMMIT();                                                           \
    }                                                                          \
    for (int ck = 0; ck < nck; ck++) {                                         \
        CP_WAIT(F16_NSTAGE - 2);                                               \
        __syncthreads();                                                       \
        int pf = ck + F16_NSTAGE - 1;                                          \
        if (pf < nck) issue_stage(pf & (F16_NSTAGE - 1), pf * BKC);            \
        CP_COMMIT();                                                           \
        uint32_t sb  = smem_base + (uint32_t)(ck & (F16_NSTAGE - 1)) * F16_STAGE; \
        uint32_t chA = sb;                                                     \
        uint32_t chB = sb + CHAC;                                              \
        _Pragma("unroll")                                                      \
        for (int t = 0; t < 2; t++) {   /* this warp's 32-wide k-half */       \
            int kk = kbase + t * 16;                                           \
            uint32_t bfr[2][4];                                                \
            _Pragma("unroll")                                                  \
            for (int p = 0; p < 2; p++) {                                      \
                uint32_t off = ((b_row + p * 16) * PADEC + kk + b_col8) * 2;   \
                ldmatrix_x4(bfr[p][0], bfr[p][1], bfr[p][2], bfr[p][3], chB + off); \
            }                                                                  \
            _Pragma("unroll")                                                  \
            for (int mi = 0; mi < 2; mi++) {                                   \
                uint32_t offA = ((a_row + mi * 16) * PADEC + kk + a_col8) * 2; \
                uint32_t a0, a1, a2, a3;                                       \
                ldmatrix_x4(a0, a1, a2, a3, chA + offA);                       \
                _Pragma("unroll")                                              \
                for (int ni = 0; ni < 4; ni++) {                               \
                    int p = ni >> 1, s = ni & 1;                               \
                    mma_f16(acc[mi][ni], a0, a1, a2, a3, bfr[p][s], bfr[p][2 + s]); \
                }                                                              \
            }                                                                  \
        }                                                                      \
    }

// Store this warp's acc into a 32x33-padded smem tile (fragment layout).
#define STORE_ACC_TILE(Cs)                                                     \
    _Pragma("unroll")                                                          \
    for (int mi = 0; mi < 2; mi++)                                             \
        _Pragma("unroll")                                                      \
        for (int ni = 0; ni < 4; ni++)                                         \
            _Pragma("unroll")                                                  \
            for (int q = 0; q < 4; q++) {                                      \
                int rl = mi * 16 + (lane >> 2) + (q >> 1) * 8;                 \
                int cl = ni * 8 + 2 * (lane & 3) + (q & 1);                    \
                (Cs)[rl * 33 + cl] = acc[mi][ni][q];                           \
            }

// Add a 32x33 smem tile into acc (inverse of STORE_ACC_TILE).
#define ADD_ACC_TILE(Cs)                                                       \
    _Pragma("unroll")                                                          \
    for (int mi = 0; mi < 2; mi++)                                             \
        _Pragma("unroll")                                                      \
        for (int ni = 0; ni < 4; ni++)                                         \
            _Pragma("unroll")                                                  \
            for (int q = 0; q < 4; q++) {                                      \
                int rl = mi * 16 + (lane >> 2) + (q >> 1) * 8;                 \
                int cl = ni * 8 + 2 * (lane & 3) + (q & 1);                    \
                acc[mi][ni][q] += (Cs)[rl * 33 + cl];                          \
            }

// ----------------------------------------------------------------------------
// Chain GEMM + fused blockdiag epilogue: H = (A·B^T)·blockdiag(Kb), fp16 out.
// Split-K merge, then warps 0-3 run the bd epilogue on their merged tiles.
// ----------------------------------------------------------------------------
__global__ void __launch_bounds__(256, 2)
gemm_bd_f16(const __half* __restrict__ A, const __half* __restrict__ B,
            const float* __restrict__ Kb, __half* __restrict__ H,
            int M, int N, int K, int do_amax) {
    extern __shared__ char smraw[];
    uint32_t smem_base = smem_u32(smraw);

    int tid  = threadIdx.x;
    int wid  = tid >> 5;
    int lane = tid & 31;
    int kw   = wid >> 2;           // k-half: 0 or 1
    int wsub = wid & 3;            // output tile id
    int m0 = blockIdx.y * 64;
    int n0 = blockIdx.x * 64;
    int wm = (wsub & 1) * 32;
    int wn = (wsub >> 1) * 32;

    CHAIN_MAINLOOP();

    // ---- split-K merge + fused blockdiag epilogue ----
    __syncthreads();                      // pipeline smem free
    float* smf = reinterpret_cast<float*>(smraw);
    float* KbS = smf;                     // 2 blocks x 32x33
    float* CsA = smf + 2 * (32 * 33);     // 4 tiles  x 32x33

    int b0 = n0 >> 5;
    for (int idx = tid; idx < 2048; idx += 256) {
        int blk = idx >> 10;
        int rem = idx & 1023;
        KbS[blk * (32 * 33) + (rem >> 5) * 33 + (rem & 31)] =
            Kb[(b0 + blk) * 1024 + rem];
    }
    if (kw == 1) {
        float* Cs = CsA + wsub * (32 * 33);
        STORE_ACC_TILE(Cs);
    }
    __syncthreads();

    if (kw == 0) {
        float* Cs = CsA + wsub * (32 * 33);
        ADD_ACC_TILE(Cs);

        int wb = wn >> 5;
        float kreg[32];
#pragma unroll
        for (int i = 0; i < 32; i++) kreg[i] = KbS[wb * (32 * 33) + i * 33 + lane];

        // restage merged tile, then multiply by the K block
        STORE_ACC_TILE(Cs);
        __syncwarp();

        float lmax = 0.f;
#pragma unroll 4
        for (int r = 0; r < 32; r++) {
            float s = 0.f;
#pragma unroll
            for (int i = 0; i < 32; i++) s += Cs[r * 33 + i] * kreg[i];
            lmax = fmaxf(lmax, fabsf(s));
            H[(size_t)(m0 + wm + r) * N + n0 + wn + lane] = __float2half_rn(s);
        }
        if (do_amax) {
#pragma unroll
            for (int o = 16; o; o >>= 1)
                lmax = fmaxf(lmax, __shfl_xor_sync(0xffffffffu, lmax, o));
            if (lane == 0) atomicMax(&g_amax_bits, __float_as_uint(lmax));
        }
    }
}

// ----------------------------------------------------------------------------
// Final chain GEMM: M8 = s8( (A·B^T) * 127/amax ), amax = amax(T0a) bound.
// ----------------------------------------------------------------------------
__global__ void __launch_bounds__(256, 2)
gemm_q_f16(const __half* __restrict__ A, const __half* __restrict__ B,
           int8_t* __restrict__ C8, int M, int N, int K) {
    extern __shared__ char smraw[];
    uint32_t smem_base = smem_u32(smraw);

    int tid  = threadIdx.x;
    int wid  = tid >> 5;
    int lane = tid & 31;
    int kw   = wid >> 2;
    int wsub = wid & 3;
    int m0 = blockIdx.y * 64;
    int n0 = blockIdx.x * 64;
    int wm = (wsub & 1) * 32;
    int wn = (wsub >> 1) * 32;

    CHAIN_MAINLOOP();

    __syncthreads();
    float* CsA = reinterpret_cast<float*>(smraw);
    if (kw == 1) {
        float* Cs = CsA + wsub * (32 * 33);
        STORE_ACC_TILE(Cs);
    }
    __syncthreads();

    if (kw == 0) {
        float* Cs = CsA + wsub * (32 * 33);
        ADD_ACC_TILE(Cs);

        float amax = __uint_as_float(g_amax_bits);
        float q = (amax > 1e-30f) ? (127.0f / amax) : 0.f;

        int g   = lane >> 2;
        int tig = lane & 3;
#pragma unroll
        for (int mi = 0; mi < 2; mi++) {
#pragma unroll
            for (int ni = 0; ni < 4; ni++) {
                int col = n0 + wn + ni * 8 + 2 * tig;
#pragma unroll
                for (int half = 0; half < 2; half++) {
                    int r = m0 + wm + mi * 16 + g + half * 8;
                    int v0 = q_s8(acc[mi][ni][half * 2 + 0], q);
                    int v1 = q_s8(acc[mi][ni][half * 2 + 1], q);
                    uint16_t pk = (uint16_t)((v0 & 255) | ((v1 & 255) << 8));
                    *reinterpret_cast<uint16_t*>(C8 + (size_t)r * N + col) = pk;
                }
            }
        }
    }
}

// ============================================================================
// s8 single-pass TN GEMM (big GEMM): C = (A*B^T)*scale + bias, fp32 out.
// BM=128, BN=256, BK=128 bytes; 16 warps (4m x 4n), warp tile 32x64;
// m16n8k32 s8 IMMA; cp.async 3-stage ring; 1 CTA/SM.
// ============================================================================
#define Q_PAD    144                            // bytes per smem row (128+16)
#define Q_CHA    (128 * Q_PAD)                  // 18432
#define Q_CHB    (256 * Q_PAD)                  // 36864
#define Q_STAGE  (Q_CHA + Q_CHB)                // 55296
#define Q_NST    3
#define Q_SMEM   (Q_NST * Q_STAGE)              // 165888
#define Q_BK     128

__global__ void __launch_bounds__(512, 1)
gemm_tn_s8(const int8_t* __restrict__ A, const int8_t* __restrict__ B,
           float* __restrict__ C, int M, int N, int K,
           const float* __restrict__ bias) {
    extern __shared__ char smraw[];
    uint32_t smem_base = smem_u32(smraw);

    int tid  = threadIdx.x;
    int wid  = tid >> 5;
    int lane = tid & 31;
    int m0 = blockIdx.y * 128;
    int n0 = blockIdx.x * 256;
    int wm = (wid & 3) * 32;
    int wn = (wid >> 2) * 64;

    uint32_t goff[6];
    uint32_t soff[6];
#pragma unroll
    for (int j = 0; j < 2; j++) {       // A
        int c = tid + j * 512;
        int row = c >> 3, cc = c & 7;
        goff[j] = (uint32_t)((m0 + row) * K + cc * 16);
        soff[j] = (uint32_t)(row * Q_PAD + cc * 16);
    }
#pragma unroll
    for (int j = 0; j < 4; j++) {       // B
        int c = tid + j * 512;
        int row = c >> 3, cc = c & 7;
        goff[2 + j] = (uint32_t)((n0 + row) * K + cc * 16);
        soff[2 + j] = (uint32_t)(Q_CHA + row * Q_PAD + cc * 16);
    }

    auto issue_stage = [&](int st, int k0) {
        uint32_t sb = smem_base + (uint32_t)st * Q_STAGE;
#pragma unroll
        for (int j = 0; j < 2; j++)
            cp_async16(sb + soff[j], A + goff[j] + k0);
#pragma unroll
        for (int j = 2; j < 6; j++)
            cp_async16(sb + soff[j], B + goff[j] + k0);
    };

    int acc[2][8][4];
#pragma unroll
    for (int i = 0; i < 2; i++)
#pragma unroll
        for (int j = 0; j < 8; j++)
#pragma unroll
            for (int q = 0; q < 4; q++) acc[i][j][q] = 0;

    int a_row  = wm + (lane & 15);
    int a_koff = (lane >> 4) * 16;
    int b_col  = wn + (lane & 7) + ((lane >> 4) & 1) * 8;
    int b_koff = ((lane >> 3) & 1) * 16;

    int nck = K / Q_BK;                 // 8
#pragma unroll
    for (int s = 0; s < Q_NST - 1; s++) {
        issue_stage(s, s * Q_BK);
        CP_COMMIT();
    }

    int st_c = 0, st_p = Q_NST - 1;
    for (int ck = 0; ck < nck; ck++) {
        CP_WAIT(Q_NST - 2);
        __syncthreads();

        int pf = ck + Q_NST - 1;
        if (pf < nck) issue_stage(st_p, pf * Q_BK);
        CP_COMMIT();
        if (++st_p == Q_NST) st_p = 0;

        uint32_t sb  = smem_base + (uint32_t)st_c * Q_STAGE;
        if (++st_c == Q_NST) st_c = 0;
        uint32_t chA = sb;
        uint32_t chB = sb + Q_CHA;

#pragma unroll
        for (int ks = 0; ks < 4; ks++) {
            uint32_t bfr[4][4];
#pragma unroll
            for (int p = 0; p < 4; p++) {
                uint32_t off = (b_col + p * 16) * Q_PAD + ks * 32 + b_koff;
                ldmatrix_x4(bfr[p][0], bfr[p][1], bfr[p][2], bfr[p][3], chB + off);
            }
#pragma unroll
            for (int mi = 0; mi < 2; mi++) {
                uint32_t offA = (a_row + mi * 16) * Q_PAD + ks * 32 + a_koff;
                uint32_t a0, a1, a2, a3;
                ldmatrix_x4(a0, a1, a2, a3, chA + offA);
#pragma unroll
                for (int ni = 0; ni < 8; ni++) {
                    int p = ni >> 1, s = ni & 1;
                    mma_s8(acc[mi][ni], a0, a1, a2, a3,
                           bfr[p][s * 2], bfr[p][s * 2 + 1]);
                }
            }
        }
    }

    float amax = __uint_as_float(g_amax_bits);
    float sxm = (XCLIP / 127.0f) * (amax / 127.0f);

    int g   = lane >> 2;
    int tig = lane & 3;
#pragma unroll
    for (int mi = 0; mi < 2; mi++) {
#pragma unroll
        for (int ni = 0; ni < 8; ni++) {
            int col = n0 + wn + ni * 8 + 2 * tig;
            float bx = bias[col], by = bias[col + 1];
            int r0 = m0 + wm + mi * 16 + g;
            *reinterpret_cast<float2*>(C + (size_t)r0 * N + col) =
                make_float2((float)acc[mi][ni][0] * sxm + bx,
                            (float)acc[mi][ni][1] * sxm + by);
            *reinterpret_cast<float2*>(C + (size_t)(r0 + 8) * N + col) =
                make_float2((float)acc[mi][ni][2] * sxm + bx,
                            (float)acc[mi][ni][3] * sxm + by);
        }
    }
}

// ============================================================================
// Launch
// ============================================================================
extern "C" void kernel_launch(void* const* d_in, const int* in_sizes, int n_in,
                              void* d_out, int out_size) {
    const float* x    = (const float*)d_in[0];
    const float* P0   = (const float*)d_in[1];
    const float* P1   = (const float*)d_in[2];
    const float* P2   = (const float*)d_in[3];
    const float* P3   = (const float*)d_in[4];
    const float* K0   = (const float*)d_in[5];
    const float* K1   = (const float*)d_in[6];
    const float* K2   = (const float*)d_in[7];
    const float* bias = (const float*)d_in[8];
    float* out = (float*)d_out;

    (void)in_sizes; (void)n_in; (void)out_size;

    cudaFuncSetAttribute(gemm_bd_f16,
                         cudaFuncAttributeMaxDynamicSharedMemorySize, F16_SMEM);
    cudaFuncSetAttribute(gemm_q_f16,
                         cudaFuncAttributeMaxDynamicSharedMemorySize, F16_SMEM);
    cudaFuncSetAttribute(gemm_tn_s8,
                         cudaFuncAttributeMaxDynamicSharedMemorySize, Q_SMEM);

    float *S0t;
    __half *S1, *S2, *S3, *T0a, *T0b;
    int8_t *M8, *x8;
    cudaGetSymbolAddress((void**)&S0t, g_S0t);
    cudaGetSymbolAddress((void**)&S1,  g_S1);
    cudaGetSymbolAddress((void**)&S2,  g_S2);
    cudaGetSymbolAddress((void**)&S3,  g_S3);
    cudaGetSymbolAddress((void**)&T0a, g_T0a);
    cudaGetSymbolAddress((void**)&T0b, g_T0b);
    cudaGetSymbolAddress((void**)&M8,  g_M8);
    cudaGetSymbolAddress((void**)&x8,  g_x8);

    dim3 bdGrid(32, DDIM / 32), bdBlk(32, 8);
    dim3 gSmall(DDIM / 64, DDIM / 64);    // (16, 16) = 256 CTAs

    // 1) Fused softmaxes (+amax reset)
    softmax4<<<dim3(DDIM, 4), 256>>>(P0, P1, P2, P3, S0t, S1, S2, S3);

    // 2) Compose W^T (blockdiags fused; split-K chain GEMMs; last bd stage
    //    records amax(T0a) >= amax(M), so the final GEMM quantizes directly).
    blockdiag16<<<bdGrid, bdBlk>>>(S0t, K0, T0a);                                  // G1
    gemm_bd_f16<<<gSmall, 256, F16_SMEM>>>(T0a, S1, K1, T0b, DDIM, DDIM, DDIM, 0); // G3
    gemm_bd_f16<<<gSmall, 256, F16_SMEM>>>(T0b, S2, K2, T0a, DDIM, DDIM, DDIM, 1); // G5 (+amax)
    gemm_q_f16<<<gSmall, 256, F16_SMEM>>>(S3, T0a, M8, DDIM, DDIM, DDIM);          // M8 s8

    // 3) Quantize x (static clip scale) to s8
    int n8 = (BDIM * DDIM) / 8;
    convert_x_s8<<<n8 / 256, 256>>>((const float4*)x, (uint2*)x8, n8);

    // 4) out[b][u] = sum_d x[b][d]·M[u][d] + bias[u]  (s8 IMMA, exact int acc)
    dim3 gBig(DDIM / 256, BDIM / 128);    // (4, 256) = 1024 CTAs
    gemm_tn_s8<<<gBig, 512, Q_SMEM>>>(x8, M8, out, BDIM, DDIM, DDIM, bias);
}